// round 8
// baseline (speedup 1.0000x reference)
#include <cuda_runtime.h>
#include <cstdint>

#define N_INST 64
#define HW 64000   // 200*320
#define MASK_ELEMS (N_INST * HW)

#define SIG_BLOCKS 592
#define TOTAL_F4 (MASK_ELEMS / 4)   // 1,024,000 float4s
#define REL_BLOCKS 260              // 2080 warps

#define Q_TOTAL 16000               // HW/4 pixel-quads
#define GRIDX2 74
#define QPB 217                     // ceil(16000/74)

// Scratch (no cudaMalloc allowed):
// g_Odup[j*64+i] = (O[i][j], O[i][j]) packed 2xf32 (transposed + duplicated)
__device__ unsigned long long g_Odup[N_INST * N_INST];
// g_T = sigmoid(mask), precomputed once
__device__ __align__(16) float g_T[MASK_ELEMS];

__device__ __forceinline__ float sigmoidf_(float x) {
    return __fdividef(1.0f, 1.0f + __expf(-x));
}

__device__ __forceinline__ unsigned long long pack2_(float lo, float hi) {
    unsigned long long d;
    asm("mov.b64 %0, {%1, %2};" : "=l"(d) : "f"(lo), "f"(hi));
    return d;
}

__device__ __forceinline__ void unpack2_(unsigned long long v, float& lo, float& hi) {
    asm("mov.b64 {%0, %1}, %2;" : "=f"(lo), "=f"(hi) : "l"(v));
}

// Packed 2xfp32 FMA (SASS FFMA2) — "=l" form, measured clean on alu pipe
__device__ __forceinline__ unsigned long long fma2_(unsigned long long a,
                                                    unsigned long long b,
                                                    unsigned long long c) {
    unsigned long long d;
    asm("fma.rn.f32x2 %0, %1, %2, %3;" : "=l"(d) : "l"(a), "l"(b), "l"(c));
    return d;
}

// ---------------------------------------------------------------------------
// Kernel 1 (fused prep): blocks [0, SIG_BLOCKS) compute g_T = sigmoid(mask)
// as a float4 stream; blocks [SIG_BLOCKS, +REL_BLOCKS) compute the O matrix
// (one warp per unordered pair i<j, both orientations at once).
// ---------------------------------------------------------------------------
__global__ void prep_kernel(const float* __restrict__ mask,
                            const float* __restrict__ bbox,
                            const int*   __restrict__ cls_idx,
                            const float* __restrict__ U_w,   // (256,80)
                            const float* __restrict__ V_w,   // (256,80)
                            const float* __restrict__ Wc_w,  // (128,4)
                            const float* __restrict__ P_w,   // (384,)
                            float* __restrict__ out_O)
{
    int tid = threadIdx.x;

    if (blockIdx.x < SIG_BLOCKS) {
        const float4* m4 = reinterpret_cast<const float4*>(mask);
        float4* t4 = reinterpret_cast<float4*>(g_T);
        for (int idx = blockIdx.x * 256 + tid; idx < TOTAL_F4;
             idx += SIG_BLOCKS * 256) {
            float4 m = m4[idx];
            float4 t;
            t.x = sigmoidf_(m.x);
            t.y = sigmoidf_(m.y);
            t.z = sigmoidf_(m.z);
            t.w = sigmoidf_(m.w);
            t4[idx] = t;
        }
        return;
    }

    int warp = ((blockIdx.x - SIG_BLOCKS) * 256 + tid) >> 5;
    int lane = tid & 31;
    const int NPAIR = (N_INST * (N_INST - 1)) / 2;   // 2016
    if (warp >= NPAIR + N_INST) return;

    if (warp >= NPAIR) {                              // diagonal zeros
        if (lane == 0) {
            int i = warp - NPAIR;
            out_O[i * 64 + i]  = 0.f;
            g_Odup[i * 64 + i] = 0ull;
        }
        return;
    }

    // decode i < j from triangular index: warp = j*(j-1)/2 + i
    int j = (int)((1.0f + sqrtf(8.0f * (float)warp + 1.0f)) * 0.5f);
    while (j * (j - 1) / 2 > warp) j--;
    while ((j + 1) * j / 2 <= warp) j++;
    int i = warp - j * (j - 1) / 2;

    int ki = cls_idx[i] - 1;
    int kj = cls_idx[j] - 1;

    float s_ij = 0.f, s_ji = 0.f;

    #pragma unroll
    for (int c = lane; c < 256; c += 32) {
        float ui = fmaxf(U_w[c * 80 + ki], 0.f);
        float uj = fmaxf(U_w[c * 80 + kj], 0.f);
        float vi = fmaxf(V_w[c * 80 + ki], 0.f);
        float vj = fmaxf(V_w[c * 80 + kj], 0.f);
        float p  = P_w[c];
        s_ij += ui * vj * p;
        s_ji += uj * vi * p;
    }

    float x0i = bbox[i * 5 + 1], y0i = bbox[i * 5 + 2];
    float x1i = bbox[i * 5 + 3], y1i = bbox[i * 5 + 4];
    float x0j = bbox[j * 5 + 1], y0j = bbox[j * 5 + 2];
    float x1j = bbox[j * 5 + 3], y1j = bbox[j * 5 + 4];
    float wi = x1i - x0i + 1.f, hi = y1i - y0i + 1.f;
    float wj = x1j - x0j + 1.f, hj = y1j - y0j + 1.f;
    float xci = x0i + 0.5f * wi, yci = y0i + 0.5f * hi;
    float xcj = x0j + 0.5f * wj, ycj = y0j + 0.5f * hj;

    float dx_ij = -(xci - xcj) / wi, dy_ij = -(yci - ycj) / hi;
    float dw_ij = __logf(wj / wi),   dh_ij = __logf(hj / hi);
    float dx_ji = -(xcj - xci) / wj, dy_ji = -(ycj - yci) / hj;
    float dw_ji = __logf(wi / wj),   dh_ji = __logf(hi / hj);

    #pragma unroll
    for (int o = lane; o < 128; o += 32) {
        float4 w4 = *reinterpret_cast<const float4*>(&Wc_w[o * 4]);
        float p = P_w[256 + o];
        float a = dx_ij * w4.x + dy_ij * w4.y + dw_ij * w4.z + dh_ij * w4.w;
        float b = dx_ji * w4.x + dy_ji * w4.y + dw_ji * w4.z + dh_ji * w4.w;
        s_ij += fmaxf(a, 0.f) * p;
        s_ji += fmaxf(b, 0.f) * p;
    }

    #pragma unroll
    for (int off = 16; off; off >>= 1) {
        s_ij += __shfl_xor_sync(0xffffffffu, s_ij, off);
        s_ji += __shfl_xor_sync(0xffffffffu, s_ji, off);
    }

    if (lane == 0) {
        float r_ij = sigmoidf_(s_ij);
        float r_ji = sigmoidf_(s_ji);
        float o_ij = fmaxf(r_ij - r_ji, 0.f);
        float o_ji = fmaxf(r_ji - r_ij, 0.f);
        out_O[i * 64 + j]  = o_ij;
        out_O[j * 64 + i]  = o_ji;
        g_Odup[j * 64 + i] = pack2_(o_ij, o_ij);   // [col j][row i]
        g_Odup[i * 64 + j] = pack2_(o_ji, o_ji);
    }
}

// ---------------------------------------------------------------------------
// Kernel 2: mask update GEMM from precomputed g_T. 4 pixels/thread, 16
// i-rows/block (blockIdx.y). Per j: one LDG.128 of t (two 64-bit packed
// operands for free), 8 LDS.128 of dup'd O feeding 32 FFMA2 (1:4 ratio).
// No MUFU, no packs in the mainloop. Grid (74,4) = 296 CTAs = 2/SM.
// ---------------------------------------------------------------------------
__global__ void __launch_bounds__(256, 2)
mask_update_kernel(const float* __restrict__ mask, float* __restrict__ out)
{
    __shared__ __align__(16) unsigned long long Osh[64 * 16];  // [j][i_local]

    int tid = threadIdx.x;
    int ibase = blockIdx.y * 16;

    #pragma unroll
    for (int k = tid; k < 1024; k += 256) {
        int j = k >> 4, il = k & 15;
        Osh[j * 16 + il] = g_Odup[j * 64 + (ibase + il)];
    }
    __syncthreads();

    int q = blockIdx.x * QPB + tid;
    bool active = (tid < QPB) && (q < Q_TOTAL);
    int p = (active ? q : 0) * 4;

    // acc[2*il+0] = (w_i at pix0, pix1); acc[2*il+1] = (pix2, pix3)
    unsigned long long acc[32];
    #pragma unroll
    for (int k = 0; k < 32; k++) acc[k] = 0ull;

    // 4-deep prefetch of t rows; ulonglong2 view = two packed operands
    ulonglong2 pf0 = *reinterpret_cast<const ulonglong2*>(g_T + p);
    ulonglong2 pf1 = *reinterpret_cast<const ulonglong2*>(g_T + (size_t)1 * HW + p);
    ulonglong2 pf2 = *reinterpret_cast<const ulonglong2*>(g_T + (size_t)2 * HW + p);
    ulonglong2 pf3 = *reinterpret_cast<const ulonglong2*>(g_T + (size_t)3 * HW + p);

    #pragma unroll 4
    for (int j = 0; j < 64; j++) {
        ulonglong2 tt = pf0;          // tt.x = (t0,t1), tt.y = (t2,t3)
        pf0 = pf1; pf1 = pf2; pf2 = pf3;
        if (j < 60)
            pf3 = *reinterpret_cast<const ulonglong2*>(g_T + (size_t)(j + 4) * HW + p);
        const ulonglong2* orow = reinterpret_cast<const ulonglong2*>(&Osh[j * 16]);
        #pragma unroll
        for (int g = 0; g < 8; g++) {
            ulonglong2 o2 = orow[g];  // dup'd O for il=2g, 2g+1
            acc[4 * g + 0] = fma2_(o2.x, tt.x, acc[4 * g + 0]);
            acc[4 * g + 1] = fma2_(o2.x, tt.y, acc[4 * g + 1]);
            acc[4 * g + 2] = fma2_(o2.y, tt.x, acc[4 * g + 2]);
            acc[4 * g + 3] = fma2_(o2.y, tt.y, acc[4 * g + 3]);
        }
    }

    if (active) {
        #pragma unroll
        for (int il = 0; il < 16; il++) {
            int i = ibase + il;
            float4 m4 = *reinterpret_cast<const float4*>(mask + (size_t)i * HW + p);
            float4 t4 = *reinterpret_cast<const float4*>(g_T  + (size_t)i * HW + p);
            float w0, w1, w2, w3;
            unpack2_(acc[2 * il + 0], w0, w1);
            unpack2_(acc[2 * il + 1], w2, w3);
            float4 r;
            r.x = m4.x - m4.x * t4.x * w0;
            r.y = m4.y - m4.y * t4.y * w1;
            r.z = m4.z - m4.z * t4.z * w2;
            r.w = m4.w - m4.w * t4.w * w3;
            *reinterpret_cast<float4*>(out + (size_t)i * HW + p) = r;
        }
    }
}

extern "C" void kernel_launch(void* const* d_in, const int* in_sizes, int n_in,
                              void* d_out, int out_size)
{
    const float* mask    = (const float*)d_in[0];
    const float* bbox    = (const float*)d_in[1];
    const int*   cls_idx = (const int*)  d_in[2];
    const float* U_w     = (const float*)d_in[3];
    const float* V_w     = (const float*)d_in[4];
    const float* Wc_w    = (const float*)d_in[5];
    const float* P_w     = (const float*)d_in[6];

    float* out_mask = (float*)d_out;                 // 4,096,000 elems
    float* out_O    = (float*)d_out + MASK_ELEMS;    // 4,096 elems

    // fused: sigmoid precompute (592 blocks) + relation O (260 blocks)
    prep_kernel<<<SIG_BLOCKS + REL_BLOCKS, 256>>>(mask, bbox, cls_idx,
                                                  U_w, V_w, Wc_w, P_w, out_O);

    // 74 quad chunks x 4 i-quarters -> 296 CTAs = 2/SM, one wave
    dim3 grid(GRIDX2, 4);
    mask_update_kernel<<<grid, 256>>>(mask, out_mask);
}

// round 9
// speedup vs baseline: 1.9620x; 1.9620x over previous
#include <cuda_runtime.h>
#include <cstdint>

#define N_INST 64
#define HW 64000   // 200*320
#define MASK_ELEMS (N_INST * HW)

#define TILE_P 256          // pixels per CTA tile
#define NTILES 250          // 64000 / 256
#define KC 16               // k-chunk (j) staged per barrier

// Scratch (no cudaMalloc):
// g_Odup[j*64+i] = (O[i][j], O[i][j]) packed 2xf32 — row j is the k-slice
__device__ unsigned long long g_Odup[N_INST * N_INST];

__device__ __forceinline__ float sigmoidf_(float x) {
    return __fdividef(1.0f, 1.0f + __expf(-x));
}

__device__ __forceinline__ unsigned long long pack2_(float lo, float hi) {
    unsigned long long d;
    asm("mov.b64 %0, {%1, %2};" : "=l"(d) : "f"(lo), "f"(hi));
    return d;
}

__device__ __forceinline__ void unpack2_(unsigned long long v, float& lo, float& hi) {
    asm("mov.b64 {%0, %1}, %2;" : "=f"(lo), "=f"(hi) : "l"(v));
}

__device__ __forceinline__ unsigned long long fma2_(unsigned long long a,
                                                    unsigned long long b,
                                                    unsigned long long c) {
    unsigned long long d;
    asm("fma.rn.f32x2 %0, %1, %2, %3;" : "=l"(d) : "l"(a), "l"(b), "l"(c));
    return d;
}

// ---------------------------------------------------------------------------
// Kernel 1: relation O (one warp per unordered pair, both orientations).
// ---------------------------------------------------------------------------
__global__ void relation_O_kernel(const float* __restrict__ bbox,
                                  const int*   __restrict__ cls_idx,
                                  const float* __restrict__ U_w,
                                  const float* __restrict__ V_w,
                                  const float* __restrict__ Wc_w,
                                  const float* __restrict__ P_w,
                                  float* __restrict__ out_O)
{
    int warp = (blockIdx.x * blockDim.x + threadIdx.x) >> 5;
    int lane = threadIdx.x & 31;
    const int NPAIR = (N_INST * (N_INST - 1)) / 2;   // 2016
    if (warp >= NPAIR + N_INST) return;

    if (warp >= NPAIR) {
        if (lane == 0) {
            int i = warp - NPAIR;
            out_O[i * 64 + i]  = 0.f;
            g_Odup[i * 64 + i] = 0ull;
        }
        return;
    }

    int j = (int)((1.0f + sqrtf(8.0f * (float)warp + 1.0f)) * 0.5f);
    while (j * (j - 1) / 2 > warp) j--;
    while ((j + 1) * j / 2 <= warp) j++;
    int i = warp - j * (j - 1) / 2;

    int ki = cls_idx[i] - 1;
    int kj = cls_idx[j] - 1;

    float s_ij = 0.f, s_ji = 0.f;

    #pragma unroll
    for (int c = lane; c < 256; c += 32) {
        float ui = fmaxf(U_w[c * 80 + ki], 0.f);
        float uj = fmaxf(U_w[c * 80 + kj], 0.f);
        float vi = fmaxf(V_w[c * 80 + ki], 0.f);
        float vj = fmaxf(V_w[c * 80 + kj], 0.f);
        float p  = P_w[c];
        s_ij += ui * vj * p;
        s_ji += uj * vi * p;
    }

    float x0i = bbox[i * 5 + 1], y0i = bbox[i * 5 + 2];
    float x1i = bbox[i * 5 + 3], y1i = bbox[i * 5 + 4];
    float x0j = bbox[j * 5 + 1], y0j = bbox[j * 5 + 2];
    float x1j = bbox[j * 5 + 3], y1j = bbox[j * 5 + 4];
    float wi = x1i - x0i + 1.f, hi = y1i - y0i + 1.f;
    float wj = x1j - x0j + 1.f, hj = y1j - y0j + 1.f;
    float xci = x0i + 0.5f * wi, yci = y0i + 0.5f * hi;
    float xcj = x0j + 0.5f * wj, ycj = y0j + 0.5f * hj;

    float dx_ij = -(xci - xcj) / wi, dy_ij = -(yci - ycj) / hi;
    float dw_ij = __logf(wj / wi),   dh_ij = __logf(hj / hi);
    float dx_ji = -(xcj - xci) / wj, dy_ji = -(ycj - yci) / hj;
    float dw_ji = __logf(wi / wj),   dh_ji = __logf(hi / hj);

    #pragma unroll
    for (int o = lane; o < 128; o += 32) {
        float4 w4 = *reinterpret_cast<const float4*>(&Wc_w[o * 4]);
        float p = P_w[256 + o];
        float a = dx_ij * w4.x + dy_ij * w4.y + dw_ij * w4.z + dh_ij * w4.w;
        float b = dx_ji * w4.x + dy_ji * w4.y + dw_ji * w4.z + dh_ji * w4.w;
        s_ij += fmaxf(a, 0.f) * p;
        s_ji += fmaxf(b, 0.f) * p;
    }

    #pragma unroll
    for (int off = 16; off; off >>= 1) {
        s_ij += __shfl_xor_sync(0xffffffffu, s_ij, off);
        s_ji += __shfl_xor_sync(0xffffffffu, s_ji, off);
    }

    if (lane == 0) {
        float r_ij = sigmoidf_(s_ij);
        float r_ji = sigmoidf_(s_ji);
        float o_ij = fmaxf(r_ij - r_ji, 0.f);
        float o_ji = fmaxf(r_ji - r_ij, 0.f);
        out_O[i * 64 + j]  = o_ij;
        out_O[j * 64 + i]  = o_ji;
        g_Odup[j * 64 + i] = pack2_(o_ij, o_ij);
        g_Odup[i * 64 + j] = pack2_(o_ji, o_ji);
    }
}

// ---------------------------------------------------------------------------
// Kernel 2: tiled GEMM  w[i,p] = sum_j O[i,j] * sigmoid(mask[j,p]).
// CTA tile: all 64 i x 256 pixels. O (dup'd) resident in smem (32KB, once).
// t staged in KC=16 row chunks (16KB), sigmoid computed during staging.
// Thread tile: 8 i x 8 p (two quads) -> 32 packed accs; per k: 6 LDS.128
// (4 broadcast O + 2 t) feeding 32 FFMA2. Epilogue recomputes sigma(mask).
// ---------------------------------------------------------------------------
__global__ void __launch_bounds__(256, 2)
mask_gemm_kernel(const float* __restrict__ mask, float* __restrict__ out)
{
    __shared__ __align__(16) unsigned long long Od[64 * 64];  // 32KB
    __shared__ __align__(16) float tS[KC * TILE_P];           // 16KB

    int tid  = threadIdx.x;
    int w    = tid >> 5;        // warp 0..7 -> i rows [w*8, w*8+8)
    int lane = tid & 31;        // quads: lane and lane+32
    int pbase = blockIdx.x * TILE_P;

    // O table copy (coalesced 8B)
    #pragma unroll
    for (int k = tid; k < 4096; k += 256) Od[k] = g_Odup[k];

    // acc[r*4+0]=(p0,p1) quadA, +1=(p2,p3) quadA, +2,+3 = quadB
    unsigned long long acc[32];
    #pragma unroll
    for (int k = 0; k < 32; k++) acc[k] = 0ull;

    #pragma unroll 1
    for (int kc = 0; kc < 4; kc++) {
        __syncthreads();   // smem free (covers Od copy on kc==0)
        // stage 16 j-rows x 256 pixels of t = sigmoid(mask)
        #pragma unroll
        for (int s = tid; s < (KC * TILE_P) / 4; s += 256) {   // 1024 float4
            int row = s >> 6;          // 0..15
            int q   = s & 63;          // 0..63
            float4 m = *reinterpret_cast<const float4*>(
                mask + (size_t)(kc * KC + row) * HW + pbase + q * 4);
            float4 t;
            t.x = sigmoidf_(m.x);
            t.y = sigmoidf_(m.y);
            t.z = sigmoidf_(m.z);
            t.w = sigmoidf_(m.w);
            *reinterpret_cast<float4*>(&tS[row * TILE_P + q * 4]) = t;
        }
        __syncthreads();

        #pragma unroll
        for (int k = 0; k < KC; k++) {
            const ulonglong2* trow =
                reinterpret_cast<const ulonglong2*>(&tS[k * TILE_P]);
            ulonglong2 tA = trow[lane];        // quadA: (t0,t1),(t2,t3)
            ulonglong2 tB = trow[32 + lane];   // quadB
            const ulonglong2* orow = reinterpret_cast<const ulonglong2*>(
                &Od[(kc * KC + k) * 64 + w * 8]);   // broadcast
            ulonglong2 o01 = orow[0];
            ulonglong2 o23 = orow[1];
            ulonglong2 o45 = orow[2];
            ulonglong2 o67 = orow[3];

            acc[ 0] = fma2_(o01.x, tA.x, acc[ 0]);
            acc[ 1] = fma2_(o01.x, tA.y, acc[ 1]);
            acc[ 2] = fma2_(o01.x, tB.x, acc[ 2]);
            acc[ 3] = fma2_(o01.x, tB.y, acc[ 3]);
            acc[ 4] = fma2_(o01.y, tA.x, acc[ 4]);
            acc[ 5] = fma2_(o01.y, tA.y, acc[ 5]);
            acc[ 6] = fma2_(o01.y, tB.x, acc[ 6]);
            acc[ 7] = fma2_(o01.y, tB.y, acc[ 7]);
            acc[ 8] = fma2_(o23.x, tA.x, acc[ 8]);
            acc[ 9] = fma2_(o23.x, tA.y, acc[ 9]);
            acc[10] = fma2_(o23.x, tB.x, acc[10]);
            acc[11] = fma2_(o23.x, tB.y, acc[11]);
            acc[12] = fma2_(o23.y, tA.x, acc[12]);
            acc[13] = fma2_(o23.y, tA.y, acc[13]);
            acc[14] = fma2_(o23.y, tB.x, acc[14]);
            acc[15] = fma2_(o23.y, tB.y, acc[15]);
            acc[16] = fma2_(o45.x, tA.x, acc[16]);
            acc[17] = fma2_(o45.x, tA.y, acc[17]);
            acc[18] = fma2_(o45.x, tB.x, acc[18]);
            acc[19] = fma2_(o45.x, tB.y, acc[19]);
            acc[20] = fma2_(o45.y, tA.x, acc[20]);
            acc[21] = fma2_(o45.y, tA.y, acc[21]);
            acc[22] = fma2_(o45.y, tB.x, acc[22]);
            acc[23] = fma2_(o45.y, tB.y, acc[23]);
            acc[24] = fma2_(o67.x, tA.x, acc[24]);
            acc[25] = fma2_(o67.x, tA.y, acc[25]);
            acc[26] = fma2_(o67.x, tB.x, acc[26]);
            acc[27] = fma2_(o67.x, tB.y, acc[27]);
            acc[28] = fma2_(o67.y, tA.x, acc[28]);
            acc[29] = fma2_(o67.y, tA.y, acc[29]);
            acc[30] = fma2_(o67.y, tB.x, acc[30]);
            acc[31] = fma2_(o67.y, tB.y, acc[31]);
        }
    }

    // epilogue: new = m - m * sigma(m) * w   (sigma recomputed, no reload of t)
    #pragma unroll
    for (int r = 0; r < 8; r++) {
        int i = w * 8 + r;
        size_t base = (size_t)i * HW + pbase;

        float4 mA = *reinterpret_cast<const float4*>(mask + base + lane * 4);
        float4 mB = *reinterpret_cast<const float4*>(mask + base + (32 + lane) * 4);

        float a0, a1, a2, a3, b0, b1, b2, b3;
        unpack2_(acc[r * 4 + 0], a0, a1);
        unpack2_(acc[r * 4 + 1], a2, a3);
        unpack2_(acc[r * 4 + 2], b0, b1);
        unpack2_(acc[r * 4 + 3], b2, b3);

        float4 rA, rB;
        rA.x = mA.x - mA.x * sigmoidf_(mA.x) * a0;
        rA.y = mA.y - mA.y * sigmoidf_(mA.y) * a1;
        rA.z = mA.z - mA.z * sigmoidf_(mA.z) * a2;
        rA.w = mA.w - mA.w * sigmoidf_(mA.w) * a3;
        rB.x = mB.x - mB.x * sigmoidf_(mB.x) * b0;
        rB.y = mB.y - mB.y * sigmoidf_(mB.y) * b1;
        rB.z = mB.z - mB.z * sigmoidf_(mB.z) * b2;
        rB.w = mB.w - mB.w * sigmoidf_(mB.w) * b3;

        *reinterpret_cast<float4*>(out + base + lane * 4)        = rA;
        *reinterpret_cast<float4*>(out + base + (32 + lane) * 4) = rB;
    }
}

extern "C" void kernel_launch(void* const* d_in, const int* in_sizes, int n_in,
                              void* d_out, int out_size)
{
    const float* mask    = (const float*)d_in[0];
    const float* bbox    = (const float*)d_in[1];
    const int*   cls_idx = (const int*)  d_in[2];
    const float* U_w     = (const float*)d_in[3];
    const float* V_w     = (const float*)d_in[4];
    const float* Wc_w    = (const float*)d_in[5];
    const float* P_w     = (const float*)d_in[6];

    float* out_mask = (float*)d_out;                 // 4,096,000 elems
    float* out_O    = (float*)d_out + MASK_ELEMS;    // 4,096 elems

    relation_O_kernel<<<260, 256>>>(bbox, cls_idx, U_w, V_w, Wc_w, P_w, out_O);

    mask_gemm_kernel<<<NTILES, 256>>>(mask, out_mask);
}